// round 7
// baseline (speedup 1.0000x reference)
#include <cuda_runtime.h>
#include <math.h>

// ---------------------------------------------------------------------------
// GaussianSceneModel — R7.
//   zero:     4 coalesced float4 stores/thread (grid-stride).
//   splat:    4 gaussians/thread, multiply-form prefilters, v4/v2 global RED;
//             lidar row-pair corners fused into red.v4 when 16B-aligned.
//   finalize: R4-proven streaming scratch->out, 4 px/thread.
// ---------------------------------------------------------------------------

#define W_IMG   1600
#define H_IMG   900
#define WL_IMG  1024
#define HL_IMG  128
#define CAM_PIX (W_IMG * H_IMG)          // 1,440,000
#define LID_PIX (WL_IMG * HL_IMG)        // 131,072
#define OFF_RGB   0
#define OFF_DEPTH (3 * CAM_PIX)
#define OFF_ALPHA (4 * CAM_PIX)
#define OFF_LD    (5 * CAM_PIX)
#define OFF_LA    (5 * CAM_PIX + LID_PIX)

#define FMIN_F ((float)(-0.4363323129985824))
#define FMAX_F ((float)(0.05235987755982988))
#define FRANGE_F ((float)(0.05235987755982988 + 0.4363323129985824))
#define TWO_PI_F ((float)(6.283185307179586))
#define SIN_FMIN_LO (-0.42261826f - 1e-4f)
#define SIN_FMAX_HI ( 0.05233596f + 1e-4f)
#define NEAR_PLANE 1.0f
#define FAR_PLANE  100.0f
#define EPS 1e-8f

// Scratch accumulators (device globals -- no allocation).
__device__ float4 g_cam4[CAM_PIX];        // (r*w, g*w, b*w, z*w)
__device__ float4 g_camA4[CAM_PIX / 4];   // sum w (scalar-indexed)
__device__ float4 g_lid4[LID_PIX / 2];    // pairs of (r*w, w) -- 16B aligned

__device__ __forceinline__ void red_add_v4(float4* addr, float a, float b,
                                           float c, float d) {
    asm volatile("red.global.add.v4.f32 [%0], {%1, %2, %3, %4};"
                 :: "l"(addr), "f"(a), "f"(b), "f"(c), "f"(d) : "memory");
}
__device__ __forceinline__ void red_add_v2(float2* addr, float a, float b) {
    asm volatile("red.global.add.v2.f32 [%0], {%1, %2};"
                 :: "l"(addr), "f"(a), "f"(b) : "memory");
}

__device__ void inv4x4(const float* m, float* invOut) {
    float inv[16];
    inv[0] = m[5]*m[10]*m[15] - m[5]*m[11]*m[14] - m[9]*m[6]*m[15] +
             m[9]*m[7]*m[14] + m[13]*m[6]*m[11] - m[13]*m[7]*m[10];
    inv[4] = -m[4]*m[10]*m[15] + m[4]*m[11]*m[14] + m[8]*m[6]*m[15] -
             m[8]*m[7]*m[14] - m[12]*m[6]*m[11] + m[12]*m[7]*m[10];
    inv[8] = m[4]*m[9]*m[15] - m[4]*m[11]*m[13] - m[8]*m[5]*m[15] +
             m[8]*m[7]*m[13] + m[12]*m[5]*m[11] - m[12]*m[7]*m[9];
    inv[12] = -m[4]*m[9]*m[14] + m[4]*m[10]*m[13] + m[8]*m[5]*m[14] -
              m[8]*m[6]*m[13] - m[12]*m[5]*m[10] + m[12]*m[6]*m[9];
    inv[1] = -m[1]*m[10]*m[15] + m[1]*m[11]*m[14] + m[9]*m[2]*m[15] -
             m[9]*m[3]*m[14] - m[13]*m[2]*m[11] + m[13]*m[3]*m[10];
    inv[5] = m[0]*m[10]*m[15] - m[0]*m[11]*m[14] - m[8]*m[2]*m[15] +
             m[8]*m[3]*m[14] + m[12]*m[2]*m[11] - m[12]*m[3]*m[10];
    inv[9] = -m[0]*m[9]*m[15] + m[0]*m[11]*m[13] + m[8]*m[1]*m[15] -
             m[8]*m[3]*m[13] - m[12]*m[1]*m[11] + m[12]*m[3]*m[9];
    inv[13] = m[0]*m[9]*m[14] - m[0]*m[10]*m[13] - m[8]*m[1]*m[14] +
              m[8]*m[2]*m[13] + m[12]*m[1]*m[10] - m[12]*m[2]*m[9];
    inv[2] = m[1]*m[6]*m[15] - m[1]*m[7]*m[14] - m[5]*m[2]*m[15] +
             m[5]*m[3]*m[14] + m[13]*m[2]*m[7] - m[13]*m[3]*m[6];
    inv[6] = -m[0]*m[6]*m[15] + m[0]*m[7]*m[14] + m[4]*m[2]*m[15] -
             m[4]*m[3]*m[14] - m[12]*m[2]*m[7] + m[12]*m[3]*m[6];
    inv[10] = m[0]*m[5]*m[15] - m[0]*m[7]*m[13] - m[4]*m[1]*m[15] +
              m[4]*m[3]*m[13] + m[12]*m[1]*m[7] - m[12]*m[3]*m[5];
    inv[14] = -m[0]*m[5]*m[14] + m[0]*m[6]*m[13] + m[4]*m[1]*m[14] -
              m[4]*m[2]*m[13] - m[12]*m[1]*m[6] + m[12]*m[2]*m[5];
    inv[3] = -m[1]*m[6]*m[11] + m[1]*m[7]*m[10] + m[5]*m[2]*m[11] -
             m[5]*m[3]*m[10] - m[9]*m[2]*m[7] + m[9]*m[3]*m[6];
    inv[7] = m[0]*m[6]*m[11] - m[0]*m[7]*m[10] - m[4]*m[2]*m[11] +
             m[4]*m[3]*m[10] + m[8]*m[2]*m[7] - m[8]*m[3]*m[6];
    inv[11] = -m[0]*m[5]*m[11] + m[0]*m[7]*m[9] + m[4]*m[1]*m[11] -
              m[4]*m[3]*m[9] - m[8]*m[1]*m[7] + m[8]*m[3]*m[5];
    inv[15] = m[0]*m[5]*m[10] - m[0]*m[6]*m[9] - m[4]*m[1]*m[10] +
              m[4]*m[2]*m[9] + m[8]*m[1]*m[6] - m[8]*m[2]*m[5];
    float det = m[0]*inv[0] + m[1]*inv[4] + m[2]*inv[8] + m[3]*inv[12];
    det = 1.0f / det;
    for (int i = 0; i < 16; i++) invOut[i] = inv[i] * det;
}

#define Z_CAM4 CAM_PIX
#define Z_CAMA (CAM_PIX / 4)
#define Z_LID  (LID_PIX / 2)
#define Z_TOT  (Z_CAM4 + Z_CAMA + Z_LID)          // 1,865,536 float4
#define Z_THREADS ((Z_TOT + 3) / 4)               // 466,384
__global__ void __launch_bounds__(256) zero_kernel() {
    int t = blockIdx.x * blockDim.x + threadIdx.x;
    const int T = Z_THREADS;
    float4 z = make_float4(0.f, 0.f, 0.f, 0.f);
    #pragma unroll
    for (int k = 0; k < 4; k++) {
        int i = t + k * T;          // coalesced across the warp each step
        if (i < Z_CAM4) {
            g_cam4[i] = z;
        } else if (i < Z_CAM4 + Z_CAMA) {
            g_camA4[i - Z_CAM4] = z;
        } else if (i < Z_TOT) {
            g_lid4[i - Z_CAM4 - Z_CAMA] = z;
        }
    }
}

__device__ __forceinline__ float sigmoid_fast(float x) {
    x = fminf(fmaxf(x, -20.0f), 20.0f);
    return __fdividef(1.0f, 1.0f + __expf(-x));
}

__device__ __forceinline__ void splat_one(
        float mx, float my, float mz, int g,
        const float* sC, const float* sL, const float* sK,
        const float* __restrict__ sh,
        const float* __restrict__ opa_c,
        const float* __restrict__ opa_l) {
    // ---------------- camera ----------------
    {
        float x = fmaf(sC[0], mx, fmaf(sC[1], my, fmaf(sC[2], mz, sC[3])));
        float y = fmaf(sC[4], mx, fmaf(sC[5], my, fmaf(sC[6], mz, sC[7])));
        float z = fmaf(sC[8], mx, fmaf(sC[9], my, fmaf(sC[10], mz, sC[11])));
        if (z > NEAR_PLANE && z < FAR_PLANE) {
            float tx = __fmul_rn(sK[0], x);
            float ty = __fmul_rn(sK[1], y);
            if (fabsf(tx) < sK[4] * z && fabsf(ty) < sK[5] * z) {
                float u = __fadd_rn(__fdiv_rn(tx, z), sK[2]);
                float v = __fadd_rn(__fdiv_rn(ty, z), sK[3]);
                float u0 = floorf(u), v0 = floorf(v);
                float fu = __fsub_rn(u, u0), fv = __fsub_rn(v, v0);
                int u0i = (int)u0, v0i = (int)v0;
                if (u0i >= -1 && u0i < W_IMG && v0i >= -1 && v0i < H_IMG) {
                    float oc = sigmoid_fast(opa_c[g]);
                    float4 shv = *(const float4*)(sh + 48*g);
                    float cr = sigmoid_fast(shv.x);
                    float cg = sigmoid_fast(shv.y);
                    float cb = sigmoid_fast(shv.z);
                    float ofu = __fsub_rn(1.0f, fu), ofv = __fsub_rn(1.0f, fv);
                    float cw[4] = { __fmul_rn(ofu, ofv), __fmul_rn(fu, ofv),
                                    __fmul_rn(ofu, fv),  __fmul_rn(fu, fv) };
                    #pragma unroll
                    for (int c = 0; c < 4; c++) {
                        int ui = u0i + (c & 1);
                        int vi = v0i + (c >> 1);
                        if (ui >= 0 && ui < W_IMG && vi >= 0 && vi < H_IMG) {
                            float ww = __fmul_rn(oc, cw[c]);
                            int pix = vi * W_IMG + ui;
                            red_add_v4(&g_cam4[pix],
                                       __fmul_rn(cr, ww), __fmul_rn(cg, ww),
                                       __fmul_rn(cb, ww), __fmul_rn(z, ww));
                            atomicAdd(&((float*)g_camA4)[pix], ww);
                        }
                    }
                }
            }
        }
    }

    // ---------------- lidar ----------------
    {
        float x = fmaf(sL[0], mx, fmaf(sL[1], my, fmaf(sL[2], mz, sL[3])));
        float y = fmaf(sL[4], mx, fmaf(sL[5], my, fmaf(sL[6], mz, sL[7])));
        float z = fmaf(sL[8], mx, fmaf(sL[9], my, fmaf(sL[10], mz, sL[11])));
        float r = sqrtf(__fadd_rn(__fadd_rn(__fmul_rn(x,x), __fmul_rn(y,y)),
                                  __fmul_rn(z,z)));
        if (r > NEAR_PLANE && r < FAR_PLANE &&
            z >= SIN_FMIN_LO * r && z <= SIN_FMAX_HI * r) {
            float s = __fdiv_rn(z, fmaxf(r, 1e-6f));
            float el = asinf(s);
            if (el >= FMIN_F && el <= FMAX_F) {
                float az = atan2f(y, x);
                float uL = __fmul_rn(__fadd_rn(__fdiv_rn(az, TWO_PI_F), 0.5f),
                                     (float)WL_IMG);
                float vL = __fmul_rn(__fdiv_rn(__fsub_rn(FMAX_F, el), FRANGE_F),
                                     (float)(HL_IMG - 1));
                float u0 = floorf(uL), v0 = floorf(vL);
                float fu = __fsub_rn(uL, u0), fv = __fsub_rn(vL, v0);
                int u0i = (int)u0, v0i = (int)v0;
                float ol = sigmoid_fast(opa_l[g]);
                float ofu = __fsub_rn(1.0f, fu), ofv = __fsub_rn(1.0f, fv);
                int ui0 = u0i & (WL_IMG - 1);
                float2* lidf2 = (float2*)g_lid4;
                #pragma unroll
                for (int dv = 0; dv < 2; dv++) {
                    int vi = v0i + dv;
                    if (vi < 0 || vi >= HL_IMG) continue;
                    float fvw = (dv == 0) ? ofv : fv;
                    float wl = __fmul_rn(ol, __fmul_rn(ofu, fvw)); // left
                    float wr = __fmul_rn(ol, __fmul_rn(fu,  fvw)); // right
                    int rowp = vi * WL_IMG + ui0;
                    if ((ui0 & 1) == 0) {
                        // even: (ui0, ui0+1) share one 16B float4, no wrap
                        red_add_v4(&g_lid4[rowp >> 1],
                                   __fmul_rn(r, wl), wl,
                                   __fmul_rn(r, wr), wr);
                    } else {
                        int ui1 = (ui0 + 1) & (WL_IMG - 1);
                        red_add_v2(&lidf2[rowp], __fmul_rn(r, wl), wl);
                        red_add_v2(&lidf2[vi * WL_IMG + ui1],
                                   __fmul_rn(r, wr), wr);
                    }
                }
            }
        }
    }
}

__global__ void __launch_bounds__(256) splat_kernel(
        const float* __restrict__ means,
        const float* __restrict__ sh,
        const float* __restrict__ opa_c,
        const float* __restrict__ opa_l,
        const float* __restrict__ c2w,
        const float* __restrict__ Kmat,
        const float* __restrict__ l2w, int n) {
    __shared__ float sC[12], sL[12], sK[6];
    if (threadIdx.x == 0) {
        float inv[16];
        inv4x4(c2w, inv);
        #pragma unroll
        for (int i = 0; i < 12; i++) sC[i] = inv[i];
        inv4x4(l2w, inv);
        #pragma unroll
        for (int i = 0; i < 12; i++) sL[i] = inv[i];
        float fx = Kmat[0], fy = Kmat[4], cx = Kmat[2], cy = Kmat[5];
        sK[0] = fx; sK[1] = fy; sK[2] = cx; sK[3] = cy;
        sK[4] = fmaxf(fabsf(-1.0f - cx), fabsf((float)W_IMG + 1.0f - cx)) + 2.0f;
        sK[5] = fmaxf(fabsf(-1.0f - cy), fabsf((float)H_IMG + 1.0f - cy)) + 2.0f;
    }
    __syncthreads();

    int t = blockIdx.x * blockDim.x + threadIdx.x;
    int g0 = 4 * t;
    if (g0 >= n) return;

    if (g0 + 3 < n) {
        const float4* m4 = (const float4*)means;
        float4 A = m4[3*t + 0];
        float4 B = m4[3*t + 1];
        float4 C = m4[3*t + 2];
        float mx[4] = { A.x, A.w, B.z, C.y };
        float my[4] = { A.y, B.x, B.w, C.z };
        float mz[4] = { A.z, B.y, C.x, C.w };
        #pragma unroll
        for (int k = 0; k < 4; k++)
            splat_one(mx[k], my[k], mz[k], g0 + k, sC, sL, sK,
                      sh, opa_c, opa_l);
    } else {
        for (int k = 0; k < 4 && g0 + k < n; k++) {
            int g = g0 + k;
            splat_one(means[3*g], means[3*g+1], means[3*g+2], g, sC, sL, sK,
                      sh, opa_c, opa_l);
        }
    }
}

// Streaming finalize: 4 cam px/thread, 4 lidar px/thread.
#define CAM_T (CAM_PIX / 4)   // 360,000
#define LID_T (LID_PIX / 4)   // 32,768
__global__ void __launch_bounds__(256) finalize_kernel(float* __restrict__ out) {
    int t = blockIdx.x * blockDim.x + threadIdx.x;
    if (t < CAM_T) {
        float4 acc[4];
        #pragma unroll
        for (int i = 0; i < 4; i++) acc[i] = g_cam4[4*t + i];
        float4 w4 = g_camA4[t];
        float w[4] = { w4.x, w4.y, w4.z, w4.w };
        float rgb[12], d[4], a[4];
        #pragma unroll
        for (int i = 0; i < 4; i++) {
            float wpe = __fadd_rn(w[i], EPS);
            a[i] = fminf(fmaxf(w[i], 0.0f), 1.0f);
            float inv = __fdiv_rn(1.0f, wpe);
            rgb[3*i+0] = __fmul_rn(__fmul_rn(acc[i].x, inv), a[i]);
            rgb[3*i+1] = __fmul_rn(__fmul_rn(acc[i].y, inv), a[i]);
            rgb[3*i+2] = __fmul_rn(__fmul_rn(acc[i].z, inv), a[i]);
            d[i] = __fmul_rn(acc[i].w, inv);
        }
        float4* rgb4 = (float4*)(out + OFF_RGB);
        float4* dep4 = (float4*)(out + OFF_DEPTH);
        float4* alp4 = (float4*)(out + OFF_ALPHA);
        rgb4[3*t + 0] = make_float4(rgb[0], rgb[1], rgb[2],  rgb[3]);
        rgb4[3*t + 1] = make_float4(rgb[4], rgb[5], rgb[6],  rgb[7]);
        rgb4[3*t + 2] = make_float4(rgb[8], rgb[9], rgb[10], rgb[11]);
        dep4[t] = make_float4(d[0], d[1], d[2], d[3]);
        alp4[t] = make_float4(a[0], a[1], a[2], a[3]);
    } else if (t < CAM_T + LID_T) {
        int j = t - CAM_T;
        float4 p0 = g_lid4[2*j + 0];   // (d0,w0,d1,w1)
        float4 p1 = g_lid4[2*j + 1];   // (d2,w2,d3,w3)
        float d[4] = { p0.x, p0.z, p1.x, p1.z };
        float w[4] = { p0.y, p0.w, p1.y, p1.w };
        #pragma unroll
        for (int i = 0; i < 4; i++) {
            d[i] = __fdiv_rn(d[i], __fadd_rn(w[i], EPS));
            w[i] = fminf(fmaxf(w[i], 0.0f), 1.0f);
        }
        float4* ld4 = (float4*)(out + OFF_LD);
        float4* la4 = (float4*)(out + OFF_LA);
        ld4[j] = make_float4(d[0], d[1], d[2], d[3]);
        la4[j] = make_float4(w[0], w[1], w[2], w[3]);
    }
}

extern "C" void kernel_launch(void* const* d_in, const int* in_sizes, int n_in,
                              void* d_out, int out_size) {
    const float* means = (const float*)d_in[0];
    const float* sh    = (const float*)d_in[3];
    const float* opa_c = (const float*)d_in[4];
    const float* opa_l = (const float*)d_in[5];
    const float* c2w   = (const float*)d_in[6];
    const float* K     = (const float*)d_in[7];
    const float* l2w   = (const float*)d_in[8];
    float* out = (float*)d_out;

    int n = in_sizes[0] / 3;

    zero_kernel<<<(Z_THREADS + 255) / 256, 256>>>();
    int nt = (n + 3) / 4;
    splat_kernel<<<(nt + 255) / 256, 256>>>(means, sh, opa_c, opa_l,
                                            c2w, K, l2w, n);
    int tot = CAM_T + LID_T;
    finalize_kernel<<<(tot + 255) / 256, 256>>>(out);
}

// round 8
// speedup vs baseline: 1.0434x; 1.0434x over previous
#include <cuda_runtime.h>
#include <math.h>

// ---------------------------------------------------------------------------
// GaussianSceneModel — R8.
//   zero:     st.global.v8.f32 (256-bit) stores, 4/thread.
//   splat:    R6-proven: 4 gaussians/thread, multiply prefilters, v4/v2 RED.
//   finalize: 8 px/thread, all traffic via ld/st.global.v8.f32.
// ---------------------------------------------------------------------------

#define W_IMG   1600
#define H_IMG   900
#define WL_IMG  1024
#define HL_IMG  128
#define CAM_PIX (W_IMG * H_IMG)          // 1,440,000
#define LID_PIX (WL_IMG * HL_IMG)        // 131,072
#define OFF_RGB   0
#define OFF_DEPTH (3 * CAM_PIX)
#define OFF_ALPHA (4 * CAM_PIX)
#define OFF_LD    (5 * CAM_PIX)
#define OFF_LA    (5 * CAM_PIX + LID_PIX)

#define FMIN_F ((float)(-0.4363323129985824))
#define FMAX_F ((float)(0.05235987755982988))
#define FRANGE_F ((float)(0.05235987755982988 + 0.4363323129985824))
#define TWO_PI_F ((float)(6.283185307179586))
#define SIN_FMIN_LO (-0.42261826f - 1e-4f)
#define SIN_FMAX_HI ( 0.05233596f + 1e-4f)
#define NEAR_PLANE 1.0f
#define FAR_PLANE  100.0f
#define EPS 1e-8f

// Scratch accumulators (device globals -- no allocation).
__device__ float4 g_cam4[CAM_PIX];        // (r*w, g*w, b*w, z*w)
__device__ float4 g_camA4[CAM_PIX / 4];   // sum w (scalar-indexed)
__device__ float4 g_lid4[LID_PIX / 2];    // pairs of (r*w, w)

__device__ __forceinline__ void red_add_v4(float4* addr, float a, float b,
                                           float c, float d) {
    asm volatile("red.global.add.v4.f32 [%0], {%1, %2, %3, %4};"
                 :: "l"(addr), "f"(a), "f"(b), "f"(c), "f"(d) : "memory");
}
__device__ __forceinline__ void red_add_v2(float2* addr, float a, float b) {
    asm volatile("red.global.add.v2.f32 [%0], {%1, %2};"
                 :: "l"(addr), "f"(a), "f"(b) : "memory");
}

// 256-bit global memory ops (sm_100+)
__device__ __forceinline__ void st_v8(float* p, float a0, float a1, float a2,
                                      float a3, float a4, float a5, float a6,
                                      float a7) {
    asm volatile("st.global.v8.f32 [%0], {%1,%2,%3,%4,%5,%6,%7,%8};"
                 :: "l"(p), "f"(a0), "f"(a1), "f"(a2), "f"(a3),
                    "f"(a4), "f"(a5), "f"(a6), "f"(a7) : "memory");
}
__device__ __forceinline__ void ld_v8(const float* p, float* r) {
    asm volatile("ld.global.v8.f32 {%0,%1,%2,%3,%4,%5,%6,%7}, [%8];"
                 : "=f"(r[0]), "=f"(r[1]), "=f"(r[2]), "=f"(r[3]),
                   "=f"(r[4]), "=f"(r[5]), "=f"(r[6]), "=f"(r[7])
                 : "l"(p));
}

__device__ void inv4x4(const float* m, float* invOut) {
    float inv[16];
    inv[0] = m[5]*m[10]*m[15] - m[5]*m[11]*m[14] - m[9]*m[6]*m[15] +
             m[9]*m[7]*m[14] + m[13]*m[6]*m[11] - m[13]*m[7]*m[10];
    inv[4] = -m[4]*m[10]*m[15] + m[4]*m[11]*m[14] + m[8]*m[6]*m[15] -
             m[8]*m[7]*m[14] - m[12]*m[6]*m[11] + m[12]*m[7]*m[10];
    inv[8] = m[4]*m[9]*m[15] - m[4]*m[11]*m[13] - m[8]*m[5]*m[15] +
             m[8]*m[7]*m[13] + m[12]*m[5]*m[11] - m[12]*m[7]*m[9];
    inv[12] = -m[4]*m[9]*m[14] + m[4]*m[10]*m[13] + m[8]*m[5]*m[14] -
              m[8]*m[6]*m[13] - m[12]*m[5]*m[10] + m[12]*m[6]*m[9];
    inv[1] = -m[1]*m[10]*m[15] + m[1]*m[11]*m[14] + m[9]*m[2]*m[15] -
             m[9]*m[3]*m[14] - m[13]*m[2]*m[11] + m[13]*m[3]*m[10];
    inv[5] = m[0]*m[10]*m[15] - m[0]*m[11]*m[14] - m[8]*m[2]*m[15] +
             m[8]*m[3]*m[14] + m[12]*m[2]*m[11] - m[12]*m[3]*m[10];
    inv[9] = -m[0]*m[9]*m[15] + m[0]*m[11]*m[13] + m[8]*m[1]*m[15] -
             m[8]*m[3]*m[13] - m[12]*m[1]*m[11] + m[12]*m[3]*m[9];
    inv[13] = m[0]*m[9]*m[14] - m[0]*m[10]*m[13] - m[8]*m[1]*m[14] +
              m[8]*m[2]*m[13] + m[12]*m[1]*m[10] - m[12]*m[2]*m[9];
    inv[2] = m[1]*m[6]*m[15] - m[1]*m[7]*m[14] - m[5]*m[2]*m[15] +
             m[5]*m[3]*m[14] + m[13]*m[2]*m[7] - m[13]*m[3]*m[6];
    inv[6] = -m[0]*m[6]*m[15] + m[0]*m[7]*m[14] + m[4]*m[2]*m[15] -
             m[4]*m[3]*m[14] - m[12]*m[2]*m[7] + m[12]*m[3]*m[6];
    inv[10] = m[0]*m[5]*m[15] - m[0]*m[7]*m[13] - m[4]*m[1]*m[15] +
              m[4]*m[3]*m[13] + m[12]*m[1]*m[7] - m[12]*m[3]*m[5];
    inv[14] = -m[0]*m[5]*m[14] + m[0]*m[6]*m[13] + m[4]*m[1]*m[14] -
              m[4]*m[2]*m[13] - m[12]*m[1]*m[6] + m[12]*m[2]*m[5];
    inv[3] = -m[1]*m[6]*m[11] + m[1]*m[7]*m[10] + m[5]*m[2]*m[11] -
             m[5]*m[3]*m[10] - m[9]*m[2]*m[7] + m[9]*m[3]*m[6];
    inv[7] = m[0]*m[6]*m[11] - m[0]*m[7]*m[10] - m[4]*m[2]*m[11] +
             m[4]*m[3]*m[10] + m[8]*m[2]*m[7] - m[8]*m[3]*m[6];
    inv[11] = -m[0]*m[5]*m[11] + m[0]*m[7]*m[9] + m[4]*m[1]*m[11] -
              m[4]*m[3]*m[9] - m[8]*m[1]*m[7] + m[8]*m[3]*m[5];
    inv[15] = m[0]*m[5]*m[10] - m[0]*m[6]*m[9] - m[4]*m[1]*m[10] +
              m[4]*m[2]*m[9] + m[8]*m[1]*m[6] - m[8]*m[2]*m[5];
    float det = m[0]*inv[0] + m[1]*inv[4] + m[2]*inv[8] + m[3]*inv[12];
    det = 1.0f / det;
    for (int i = 0; i < 16; i++) invOut[i] = inv[i] * det;
}

// ---- zero: v8 stores ----
#define N_CAM4_V8 (CAM_PIX / 2)            // 720,000 (each v8 = 2 float4)
#define N_CAMA_V8 (CAM_PIX / 8)            // 180,000
#define N_LID_V8  (LID_PIX / 4)            // 32,768
#define TOT_V8    (N_CAM4_V8 + N_CAMA_V8 + N_LID_V8)   // 932,768
#define Z_THREADS ((TOT_V8 + 3) / 4)                   // 233,192
__global__ void __launch_bounds__(256) zero_kernel() {
    int t = blockIdx.x * blockDim.x + threadIdx.x;
    const int T = Z_THREADS;
    #pragma unroll
    for (int k = 0; k < 4; k++) {
        int i = t + k * T;
        float* p;
        if (i < N_CAM4_V8) {
            p = (float*)g_cam4 + 8 * i;
        } else if (i < N_CAM4_V8 + N_CAMA_V8) {
            p = (float*)g_camA4 + 8 * (i - N_CAM4_V8);
        } else if (i < TOT_V8) {
            p = (float*)g_lid4 + 8 * (i - N_CAM4_V8 - N_CAMA_V8);
        } else {
            continue;
        }
        st_v8(p, 0.f, 0.f, 0.f, 0.f, 0.f, 0.f, 0.f, 0.f);
    }
}

__device__ __forceinline__ float sigmoid_fast(float x) {
    x = fminf(fmaxf(x, -20.0f), 20.0f);
    return __fdividef(1.0f, 1.0f + __expf(-x));
}

__device__ __forceinline__ void splat_one(
        float mx, float my, float mz, int g,
        const float* sC, const float* sL, const float* sK,
        const float* __restrict__ sh,
        const float* __restrict__ opa_c,
        const float* __restrict__ opa_l) {
    // ---------------- camera ----------------
    {
        float x = fmaf(sC[0], mx, fmaf(sC[1], my, fmaf(sC[2], mz, sC[3])));
        float y = fmaf(sC[4], mx, fmaf(sC[5], my, fmaf(sC[6], mz, sC[7])));
        float z = fmaf(sC[8], mx, fmaf(sC[9], my, fmaf(sC[10], mz, sC[11])));
        if (z > NEAR_PLANE && z < FAR_PLANE) {
            float tx = __fmul_rn(sK[0], x);
            float ty = __fmul_rn(sK[1], y);
            if (fabsf(tx) < sK[4] * z && fabsf(ty) < sK[5] * z) {
                float u = __fadd_rn(__fdiv_rn(tx, z), sK[2]);
                float v = __fadd_rn(__fdiv_rn(ty, z), sK[3]);
                float u0 = floorf(u), v0 = floorf(v);
                float fu = __fsub_rn(u, u0), fv = __fsub_rn(v, v0);
                int u0i = (int)u0, v0i = (int)v0;
                if (u0i >= -1 && u0i < W_IMG && v0i >= -1 && v0i < H_IMG) {
                    float oc = sigmoid_fast(opa_c[g]);
                    float4 shv = *(const float4*)(sh + 48*g);
                    float cr = sigmoid_fast(shv.x);
                    float cg = sigmoid_fast(shv.y);
                    float cb = sigmoid_fast(shv.z);
                    float ofu = __fsub_rn(1.0f, fu), ofv = __fsub_rn(1.0f, fv);
                    float cw[4] = { __fmul_rn(ofu, ofv), __fmul_rn(fu, ofv),
                                    __fmul_rn(ofu, fv),  __fmul_rn(fu, fv) };
                    #pragma unroll
                    for (int c = 0; c < 4; c++) {
                        int ui = u0i + (c & 1);
                        int vi = v0i + (c >> 1);
                        if (ui >= 0 && ui < W_IMG && vi >= 0 && vi < H_IMG) {
                            float ww = __fmul_rn(oc, cw[c]);
                            int pix = vi * W_IMG + ui;
                            red_add_v4(&g_cam4[pix],
                                       __fmul_rn(cr, ww), __fmul_rn(cg, ww),
                                       __fmul_rn(cb, ww), __fmul_rn(z, ww));
                            atomicAdd(&((float*)g_camA4)[pix], ww);
                        }
                    }
                }
            }
        }
    }

    // ---------------- lidar ----------------
    {
        float x = fmaf(sL[0], mx, fmaf(sL[1], my, fmaf(sL[2], mz, sL[3])));
        float y = fmaf(sL[4], mx, fmaf(sL[5], my, fmaf(sL[6], mz, sL[7])));
        float z = fmaf(sL[8], mx, fmaf(sL[9], my, fmaf(sL[10], mz, sL[11])));
        float r = sqrtf(__fadd_rn(__fadd_rn(__fmul_rn(x,x), __fmul_rn(y,y)),
                                  __fmul_rn(z,z)));
        if (r > NEAR_PLANE && r < FAR_PLANE &&
            z >= SIN_FMIN_LO * r && z <= SIN_FMAX_HI * r) {
            float s = __fdiv_rn(z, fmaxf(r, 1e-6f));
            float el = asinf(s);
            if (el >= FMIN_F && el <= FMAX_F) {
                float az = atan2f(y, x);
                float uL = __fmul_rn(__fadd_rn(__fdiv_rn(az, TWO_PI_F), 0.5f),
                                     (float)WL_IMG);
                float vL = __fmul_rn(__fdiv_rn(__fsub_rn(FMAX_F, el), FRANGE_F),
                                     (float)(HL_IMG - 1));
                float u0 = floorf(uL), v0 = floorf(vL);
                float fu = __fsub_rn(uL, u0), fv = __fsub_rn(vL, v0);
                int u0i = (int)u0, v0i = (int)v0;
                float ol = sigmoid_fast(opa_l[g]);
                float ofu = __fsub_rn(1.0f, fu), ofv = __fsub_rn(1.0f, fv);
                float cw[4] = { __fmul_rn(ofu, ofv), __fmul_rn(fu, ofv),
                                __fmul_rn(ofu, fv),  __fmul_rn(fu, fv) };
                float2* lidf2 = (float2*)g_lid4;
                #pragma unroll
                for (int c = 0; c < 4; c++) {
                    int ui = (u0i + (c & 1)) & (WL_IMG - 1);
                    int vi = v0i + (c >> 1);
                    if (vi >= 0 && vi < HL_IMG) {
                        float ww = __fmul_rn(ol, cw[c]);
                        int pix = vi * WL_IMG + ui;
                        red_add_v2(&lidf2[pix], __fmul_rn(r, ww), ww);
                    }
                }
            }
        }
    }
}

__global__ void __launch_bounds__(256) splat_kernel(
        const float* __restrict__ means,
        const float* __restrict__ sh,
        const float* __restrict__ opa_c,
        const float* __restrict__ opa_l,
        const float* __restrict__ c2w,
        const float* __restrict__ Kmat,
        const float* __restrict__ l2w, int n) {
    __shared__ float sC[12], sL[12], sK[6];
    if (threadIdx.x == 0) {
        float inv[16];
        inv4x4(c2w, inv);
        #pragma unroll
        for (int i = 0; i < 12; i++) sC[i] = inv[i];
        inv4x4(l2w, inv);
        #pragma unroll
        for (int i = 0; i < 12; i++) sL[i] = inv[i];
        float fx = Kmat[0], fy = Kmat[4], cx = Kmat[2], cy = Kmat[5];
        sK[0] = fx; sK[1] = fy; sK[2] = cx; sK[3] = cy;
        sK[4] = fmaxf(fabsf(-1.0f - cx), fabsf((float)W_IMG + 1.0f - cx)) + 2.0f;
        sK[5] = fmaxf(fabsf(-1.0f - cy), fabsf((float)H_IMG + 1.0f - cy)) + 2.0f;
    }
    __syncthreads();

    int t = blockIdx.x * blockDim.x + threadIdx.x;
    int g0 = 4 * t;
    if (g0 >= n) return;

    if (g0 + 3 < n) {
        const float4* m4 = (const float4*)means;
        float4 A = m4[3*t + 0];
        float4 B = m4[3*t + 1];
        float4 C = m4[3*t + 2];
        float mx[4] = { A.x, A.w, B.z, C.y };
        float my[4] = { A.y, B.x, B.w, C.z };
        float mz[4] = { A.z, B.y, C.x, C.w };
        #pragma unroll
        for (int k = 0; k < 4; k++)
            splat_one(mx[k], my[k], mz[k], g0 + k, sC, sL, sK,
                      sh, opa_c, opa_l);
    } else {
        for (int k = 0; k < 4 && g0 + k < n; k++) {
            int g = g0 + k;
            splat_one(means[3*g], means[3*g+1], means[3*g+2], g, sC, sL, sK,
                      sh, opa_c, opa_l);
        }
    }
}

// Finalize: 8 px/thread, all v8 traffic.
#define CAM_T8 (CAM_PIX / 8)   // 180,000
#define LID_T8 (LID_PIX / 8)   // 16,384
__global__ void __launch_bounds__(256) finalize_kernel(float* __restrict__ out) {
    int t = blockIdx.x * blockDim.x + threadIdx.x;
    if (t < CAM_T8) {
        float acc[32];               // 8 pixels x (rw,gw,bw,zw)
        const float* accp = (const float*)g_cam4 + 32 * t;
        ld_v8(accp +  0, acc +  0);
        ld_v8(accp +  8, acc +  8);
        ld_v8(accp + 16, acc + 16);
        ld_v8(accp + 24, acc + 24);
        float w[8];
        ld_v8((const float*)g_camA4 + 8 * t, w);
        float rgb[24], d[8], a[8];
        #pragma unroll
        for (int i = 0; i < 8; i++) {
            float wpe = __fadd_rn(w[i], EPS);
            a[i] = fminf(fmaxf(w[i], 0.0f), 1.0f);
            float inv = __fdiv_rn(1.0f, wpe);
            rgb[3*i+0] = __fmul_rn(__fmul_rn(acc[4*i+0], inv), a[i]);
            rgb[3*i+1] = __fmul_rn(__fmul_rn(acc[4*i+1], inv), a[i]);
            rgb[3*i+2] = __fmul_rn(__fmul_rn(acc[4*i+2], inv), a[i]);
            d[i] = __fmul_rn(acc[4*i+3], inv);
        }
        float* rgbp = out + OFF_RGB + 24 * t;   // byte 96t, 32B-aligned
        st_v8(rgbp + 0,  rgb[0],  rgb[1],  rgb[2],  rgb[3],
                         rgb[4],  rgb[5],  rgb[6],  rgb[7]);
        st_v8(rgbp + 8,  rgb[8],  rgb[9],  rgb[10], rgb[11],
                         rgb[12], rgb[13], rgb[14], rgb[15]);
        st_v8(rgbp + 16, rgb[16], rgb[17], rgb[18], rgb[19],
                         rgb[20], rgb[21], rgb[22], rgb[23]);
        st_v8(out + OFF_DEPTH + 8*t, d[0], d[1], d[2], d[3],
                                     d[4], d[5], d[6], d[7]);
        st_v8(out + OFF_ALPHA + 8*t, a[0], a[1], a[2], a[3],
                                     a[4], a[5], a[6], a[7]);
    } else if (t < CAM_T8 + LID_T8) {
        int j = t - CAM_T8;
        float p[16];                 // 8 pixels x (d,w) interleaved
        const float* lp = (const float*)g_lid4 + 16 * j;
        ld_v8(lp + 0, p + 0);
        ld_v8(lp + 8, p + 8);
        float d[8], w[8];
        #pragma unroll
        for (int i = 0; i < 8; i++) {
            d[i] = __fdiv_rn(p[2*i], __fadd_rn(p[2*i+1], EPS));
            w[i] = fminf(fmaxf(p[2*i+1], 0.0f), 1.0f);
        }
        st_v8(out + OFF_LD + 8*j, d[0], d[1], d[2], d[3],
                                  d[4], d[5], d[6], d[7]);
        st_v8(out + OFF_LA + 8*j, w[0], w[1], w[2], w[3],
                                  w[4], w[5], w[6], w[7]);
    }
}

extern "C" void kernel_launch(void* const* d_in, const int* in_sizes, int n_in,
                              void* d_out, int out_size) {
    const float* means = (const float*)d_in[0];
    const float* sh    = (const float*)d_in[3];
    const float* opa_c = (const float*)d_in[4];
    const float* opa_l = (const float*)d_in[5];
    const float* c2w   = (const float*)d_in[6];
    const float* K     = (const float*)d_in[7];
    const float* l2w   = (const float*)d_in[8];
    float* out = (float*)d_out;

    int n = in_sizes[0] / 3;

    zero_kernel<<<(Z_THREADS + 255) / 256, 256>>>();
    int nt = (n + 3) / 4;
    splat_kernel<<<(nt + 255) / 256, 256>>>(means, sh, opa_c, opa_l,
                                            c2w, K, l2w, n);
    int tot = CAM_T8 + LID_T8;
    finalize_kernel<<<(tot + 255) / 256, 256>>>(out);
}

// round 9
// speedup vs baseline: 1.2656x; 1.2130x over previous
#include <cuda_runtime.h>
#include <math.h>

// ---------------------------------------------------------------------------
// GaussianSceneModel — R9: two-launch, zero-pass-free.
//   splat:    R6/R8-proven: 4 gaussians/thread, multiply prefilters, v4/v2 RED
//             into device-global scratch (invariant: all-zero on entry).
//   finalize: streaming scratch->out; conditionally self-cleans camera scratch
//             (only where w != 0) and unconditionally self-cleans lidar
//             scratch, restoring the all-zero invariant for the next replay.
// ---------------------------------------------------------------------------

#define W_IMG   1600
#define H_IMG   900
#define WL_IMG  1024
#define HL_IMG  128
#define CAM_PIX (W_IMG * H_IMG)          // 1,440,000
#define LID_PIX (WL_IMG * HL_IMG)        // 131,072
#define OFF_RGB   0
#define OFF_DEPTH (3 * CAM_PIX)
#define OFF_ALPHA (4 * CAM_PIX)
#define OFF_LD    (5 * CAM_PIX)
#define OFF_LA    (5 * CAM_PIX + LID_PIX)

#define FMIN_F ((float)(-0.4363323129985824))
#define FMAX_F ((float)(0.05235987755982988))
#define FRANGE_F ((float)(0.05235987755982988 + 0.4363323129985824))
#define TWO_PI_F ((float)(6.283185307179586))
#define SIN_FMIN_LO (-0.42261826f - 1e-4f)
#define SIN_FMAX_HI ( 0.05233596f + 1e-4f)
#define NEAR_PLANE 1.0f
#define FAR_PLANE  100.0f
#define EPS 1e-8f

// Scratch accumulators. Device globals are zero-initialized at module load;
// finalize restores all-zero after every call (conditional self-clean).
__device__ float4 g_cam4[CAM_PIX];        // (r*w, g*w, b*w, z*w)
__device__ float4 g_camA4[CAM_PIX / 4];   // sum w (scalar-indexed)
__device__ float4 g_lid4[LID_PIX / 2];    // pairs of (r*w, w)

__device__ __forceinline__ void red_add_v4(float4* addr, float a, float b,
                                           float c, float d) {
    asm volatile("red.global.add.v4.f32 [%0], {%1, %2, %3, %4};"
                 :: "l"(addr), "f"(a), "f"(b), "f"(c), "f"(d) : "memory");
}
__device__ __forceinline__ void red_add_v2(float2* addr, float a, float b) {
    asm volatile("red.global.add.v2.f32 [%0], {%1, %2};"
                 :: "l"(addr), "f"(a), "f"(b) : "memory");
}

// 256-bit global memory ops (sm_100+)
__device__ __forceinline__ void st_v8(float* p, float a0, float a1, float a2,
                                      float a3, float a4, float a5, float a6,
                                      float a7) {
    asm volatile("st.global.v8.f32 [%0], {%1,%2,%3,%4,%5,%6,%7,%8};"
                 :: "l"(p), "f"(a0), "f"(a1), "f"(a2), "f"(a3),
                    "f"(a4), "f"(a5), "f"(a6), "f"(a7) : "memory");
}
__device__ __forceinline__ void ld_v8(const float* p, float* r) {
    asm volatile("ld.global.v8.f32 {%0,%1,%2,%3,%4,%5,%6,%7}, [%8];"
                 : "=f"(r[0]), "=f"(r[1]), "=f"(r[2]), "=f"(r[3]),
                   "=f"(r[4]), "=f"(r[5]), "=f"(r[6]), "=f"(r[7])
                 : "l"(p));
}

__device__ void inv4x4(const float* m, float* invOut) {
    float inv[16];
    inv[0] = m[5]*m[10]*m[15] - m[5]*m[11]*m[14] - m[9]*m[6]*m[15] +
             m[9]*m[7]*m[14] + m[13]*m[6]*m[11] - m[13]*m[7]*m[10];
    inv[4] = -m[4]*m[10]*m[15] + m[4]*m[11]*m[14] + m[8]*m[6]*m[15] -
             m[8]*m[7]*m[14] - m[12]*m[6]*m[11] + m[12]*m[7]*m[10];
    inv[8] = m[4]*m[9]*m[15] - m[4]*m[11]*m[13] - m[8]*m[5]*m[15] +
             m[8]*m[7]*m[13] + m[12]*m[5]*m[11] - m[12]*m[7]*m[9];
    inv[12] = -m[4]*m[9]*m[14] + m[4]*m[10]*m[13] + m[8]*m[5]*m[14] -
              m[8]*m[6]*m[13] - m[12]*m[5]*m[10] + m[12]*m[6]*m[9];
    inv[1] = -m[1]*m[10]*m[15] + m[1]*m[11]*m[14] + m[9]*m[2]*m[15] -
             m[9]*m[3]*m[14] - m[13]*m[2]*m[11] + m[13]*m[3]*m[10];
    inv[5] = m[0]*m[10]*m[15] - m[0]*m[11]*m[14] - m[8]*m[2]*m[15] +
             m[8]*m[3]*m[14] + m[12]*m[2]*m[11] - m[12]*m[3]*m[10];
    inv[9] = -m[0]*m[9]*m[15] + m[0]*m[11]*m[13] + m[8]*m[1]*m[15] -
             m[8]*m[3]*m[13] - m[12]*m[1]*m[11] + m[12]*m[3]*m[9];
    inv[13] = m[0]*m[9]*m[14] - m[0]*m[10]*m[13] - m[8]*m[1]*m[14] +
              m[8]*m[2]*m[13] + m[12]*m[1]*m[10] - m[12]*m[2]*m[9];
    inv[2] = m[1]*m[6]*m[15] - m[1]*m[7]*m[14] - m[5]*m[2]*m[15] +
             m[5]*m[3]*m[14] + m[13]*m[2]*m[7] - m[13]*m[3]*m[6];
    inv[6] = -m[0]*m[6]*m[15] + m[0]*m[7]*m[14] + m[4]*m[2]*m[15] -
             m[4]*m[3]*m[14] - m[12]*m[2]*m[7] + m[12]*m[3]*m[6];
    inv[10] = m[0]*m[5]*m[15] - m[0]*m[7]*m[13] - m[4]*m[1]*m[15] +
              m[4]*m[3]*m[13] + m[12]*m[1]*m[7] - m[12]*m[3]*m[5];
    inv[14] = -m[0]*m[5]*m[14] + m[0]*m[6]*m[13] + m[4]*m[1]*m[14] -
              m[4]*m[2]*m[13] - m[12]*m[1]*m[6] + m[12]*m[2]*m[5];
    inv[3] = -m[1]*m[6]*m[11] + m[1]*m[7]*m[10] + m[5]*m[2]*m[11] -
             m[5]*m[3]*m[10] - m[9]*m[2]*m[7] + m[9]*m[3]*m[6];
    inv[7] = m[0]*m[6]*m[11] - m[0]*m[7]*m[10] - m[4]*m[2]*m[11] +
             m[4]*m[3]*m[10] + m[8]*m[2]*m[7] - m[8]*m[3]*m[6];
    inv[11] = -m[0]*m[5]*m[11] + m[0]*m[7]*m[9] + m[4]*m[1]*m[11] -
              m[4]*m[3]*m[9] - m[8]*m[1]*m[7] + m[8]*m[3]*m[5];
    inv[15] = m[0]*m[5]*m[10] - m[0]*m[6]*m[9] - m[4]*m[1]*m[10] +
              m[4]*m[2]*m[9] + m[8]*m[1]*m[6] - m[8]*m[2]*m[5];
    float det = m[0]*inv[0] + m[1]*inv[4] + m[2]*inv[8] + m[3]*inv[12];
    det = 1.0f / det;
    for (int i = 0; i < 16; i++) invOut[i] = inv[i] * det;
}

__device__ __forceinline__ float sigmoid_fast(float x) {
    x = fminf(fmaxf(x, -20.0f), 20.0f);
    return __fdividef(1.0f, 1.0f + __expf(-x));
}

__device__ __forceinline__ void splat_one(
        float mx, float my, float mz, int g,
        const float* sC, const float* sL, const float* sK,
        const float* __restrict__ sh,
        const float* __restrict__ opa_c,
        const float* __restrict__ opa_l) {
    // ---------------- camera ----------------
    {
        float x = fmaf(sC[0], mx, fmaf(sC[1], my, fmaf(sC[2], mz, sC[3])));
        float y = fmaf(sC[4], mx, fmaf(sC[5], my, fmaf(sC[6], mz, sC[7])));
        float z = fmaf(sC[8], mx, fmaf(sC[9], my, fmaf(sC[10], mz, sC[11])));
        if (z > NEAR_PLANE && z < FAR_PLANE) {
            float tx = __fmul_rn(sK[0], x);
            float ty = __fmul_rn(sK[1], y);
            if (fabsf(tx) < sK[4] * z && fabsf(ty) < sK[5] * z) {
                float u = __fadd_rn(__fdiv_rn(tx, z), sK[2]);
                float v = __fadd_rn(__fdiv_rn(ty, z), sK[3]);
                float u0 = floorf(u), v0 = floorf(v);
                float fu = __fsub_rn(u, u0), fv = __fsub_rn(v, v0);
                int u0i = (int)u0, v0i = (int)v0;
                if (u0i >= -1 && u0i < W_IMG && v0i >= -1 && v0i < H_IMG) {
                    float oc = sigmoid_fast(opa_c[g]);
                    float4 shv = *(const float4*)(sh + 48*g);
                    float cr = sigmoid_fast(shv.x);
                    float cg = sigmoid_fast(shv.y);
                    float cb = sigmoid_fast(shv.z);
                    float ofu = __fsub_rn(1.0f, fu), ofv = __fsub_rn(1.0f, fv);
                    float cw[4] = { __fmul_rn(ofu, ofv), __fmul_rn(fu, ofv),
                                    __fmul_rn(ofu, fv),  __fmul_rn(fu, fv) };
                    #pragma unroll
                    for (int c = 0; c < 4; c++) {
                        int ui = u0i + (c & 1);
                        int vi = v0i + (c >> 1);
                        if (ui >= 0 && ui < W_IMG && vi >= 0 && vi < H_IMG) {
                            float ww = __fmul_rn(oc, cw[c]);
                            int pix = vi * W_IMG + ui;
                            red_add_v4(&g_cam4[pix],
                                       __fmul_rn(cr, ww), __fmul_rn(cg, ww),
                                       __fmul_rn(cb, ww), __fmul_rn(z, ww));
                            atomicAdd(&((float*)g_camA4)[pix], ww);
                        }
                    }
                }
            }
        }
    }

    // ---------------- lidar ----------------
    {
        float x = fmaf(sL[0], mx, fmaf(sL[1], my, fmaf(sL[2], mz, sL[3])));
        float y = fmaf(sL[4], mx, fmaf(sL[5], my, fmaf(sL[6], mz, sL[7])));
        float z = fmaf(sL[8], mx, fmaf(sL[9], my, fmaf(sL[10], mz, sL[11])));
        float r = sqrtf(__fadd_rn(__fadd_rn(__fmul_rn(x,x), __fmul_rn(y,y)),
                                  __fmul_rn(z,z)));
        if (r > NEAR_PLANE && r < FAR_PLANE &&
            z >= SIN_FMIN_LO * r && z <= SIN_FMAX_HI * r) {
            float s = __fdiv_rn(z, fmaxf(r, 1e-6f));
            float el = asinf(s);
            if (el >= FMIN_F && el <= FMAX_F) {
                float az = atan2f(y, x);
                float uL = __fmul_rn(__fadd_rn(__fdiv_rn(az, TWO_PI_F), 0.5f),
                                     (float)WL_IMG);
                float vL = __fmul_rn(__fdiv_rn(__fsub_rn(FMAX_F, el), FRANGE_F),
                                     (float)(HL_IMG - 1));
                float u0 = floorf(uL), v0 = floorf(vL);
                float fu = __fsub_rn(uL, u0), fv = __fsub_rn(vL, v0);
                int u0i = (int)u0, v0i = (int)v0;
                float ol = sigmoid_fast(opa_l[g]);
                float ofu = __fsub_rn(1.0f, fu), ofv = __fsub_rn(1.0f, fv);
                float cw[4] = { __fmul_rn(ofu, ofv), __fmul_rn(fu, ofv),
                                __fmul_rn(ofu, fv),  __fmul_rn(fu, fv) };
                float2* lidf2 = (float2*)g_lid4;
                #pragma unroll
                for (int c = 0; c < 4; c++) {
                    int ui = (u0i + (c & 1)) & (WL_IMG - 1);
                    int vi = v0i + (c >> 1);
                    if (vi >= 0 && vi < HL_IMG) {
                        float ww = __fmul_rn(ol, cw[c]);
                        int pix = vi * WL_IMG + ui;
                        red_add_v2(&lidf2[pix], __fmul_rn(r, ww), ww);
                    }
                }
            }
        }
    }
}

__global__ void __launch_bounds__(256) splat_kernel(
        const float* __restrict__ means,
        const float* __restrict__ sh,
        const float* __restrict__ opa_c,
        const float* __restrict__ opa_l,
        const float* __restrict__ c2w,
        const float* __restrict__ Kmat,
        const float* __restrict__ l2w, int n) {
    __shared__ float sC[12], sL[12], sK[6];
    if (threadIdx.x == 0) {
        float inv[16];
        inv4x4(c2w, inv);
        #pragma unroll
        for (int i = 0; i < 12; i++) sC[i] = inv[i];
        inv4x4(l2w, inv);
        #pragma unroll
        for (int i = 0; i < 12; i++) sL[i] = inv[i];
        float fx = Kmat[0], fy = Kmat[4], cx = Kmat[2], cy = Kmat[5];
        sK[0] = fx; sK[1] = fy; sK[2] = cx; sK[3] = cy;
        sK[4] = fmaxf(fabsf(-1.0f - cx), fabsf((float)W_IMG + 1.0f - cx)) + 2.0f;
        sK[5] = fmaxf(fabsf(-1.0f - cy), fabsf((float)H_IMG + 1.0f - cy)) + 2.0f;
    }
    __syncthreads();

    int t = blockIdx.x * blockDim.x + threadIdx.x;
    int g0 = 4 * t;
    if (g0 >= n) return;

    if (g0 + 3 < n) {
        const float4* m4 = (const float4*)means;
        float4 A = m4[3*t + 0];
        float4 B = m4[3*t + 1];
        float4 C = m4[3*t + 2];
        float mx[4] = { A.x, A.w, B.z, C.y };
        float my[4] = { A.y, B.x, B.w, C.z };
        float mz[4] = { A.z, B.y, C.x, C.w };
        #pragma unroll
        for (int k = 0; k < 4; k++)
            splat_one(mx[k], my[k], mz[k], g0 + k, sC, sL, sK,
                      sh, opa_c, opa_l);
    } else {
        for (int k = 0; k < 4 && g0 + k < n; k++) {
            int g = g0 + k;
            splat_one(means[3*g], means[3*g+1], means[3*g+2], g, sC, sL, sK,
                      sh, opa_c, opa_l);
        }
    }
}

// Finalize: 8 px/thread; conditional camera self-clean restores the
// all-zero scratch invariant without a separate zero pass.
#define CAM_T8 (CAM_PIX / 8)   // 180,000
#define LID_T8 (LID_PIX / 8)   // 16,384
__global__ void __launch_bounds__(256) finalize_kernel(float* __restrict__ out) {
    int t = blockIdx.x * blockDim.x + threadIdx.x;
    const float4 z4 = make_float4(0.f, 0.f, 0.f, 0.f);
    if (t < CAM_T8) {
        float w[8];
        ld_v8((const float*)g_camA4 + 8 * t, w);
        bool any = false;
        #pragma unroll
        for (int i = 0; i < 8; i++) any = any || (w[i] != 0.0f);

        float4 acc[8];
        #pragma unroll
        for (int i = 0; i < 8; i++) {
            // predicated load: untouched pixels are zero by invariant
            acc[i] = (w[i] != 0.0f) ? g_cam4[8*t + i] : z4;
        }
        float rgb[24], d[8], a[8];
        #pragma unroll
        for (int i = 0; i < 8; i++) {
            float wpe = __fadd_rn(w[i], EPS);
            a[i] = fminf(fmaxf(w[i], 0.0f), 1.0f);
            float inv = __fdiv_rn(1.0f, wpe);
            rgb[3*i+0] = __fmul_rn(__fmul_rn(acc[i].x, inv), a[i]);
            rgb[3*i+1] = __fmul_rn(__fmul_rn(acc[i].y, inv), a[i]);
            rgb[3*i+2] = __fmul_rn(__fmul_rn(acc[i].z, inv), a[i]);
            d[i] = __fmul_rn(acc[i].w, inv);
        }
        float* rgbp = out + OFF_RGB + 24 * t;
        st_v8(rgbp + 0,  rgb[0],  rgb[1],  rgb[2],  rgb[3],
                         rgb[4],  rgb[5],  rgb[6],  rgb[7]);
        st_v8(rgbp + 8,  rgb[8],  rgb[9],  rgb[10], rgb[11],
                         rgb[12], rgb[13], rgb[14], rgb[15]);
        st_v8(rgbp + 16, rgb[16], rgb[17], rgb[18], rgb[19],
                         rgb[20], rgb[21], rgb[22], rgb[23]);
        st_v8(out + OFF_DEPTH + 8*t, d[0], d[1], d[2], d[3],
                                     d[4], d[5], d[6], d[7]);
        st_v8(out + OFF_ALPHA + 8*t, a[0], a[1], a[2], a[3],
                                     a[4], a[5], a[6], a[7]);
        // self-clean only where touched
        if (any) {
            st_v8((float*)g_camA4 + 8*t, 0.f, 0.f, 0.f, 0.f,
                                         0.f, 0.f, 0.f, 0.f);
            #pragma unroll
            for (int i = 0; i < 8; i++)
                if (w[i] != 0.0f) g_cam4[8*t + i] = z4;
        }
    } else if (t < CAM_T8 + LID_T8) {
        int j = t - CAM_T8;
        float p[16];
        float* lp = (float*)g_lid4 + 16 * j;
        ld_v8(lp + 0, p + 0);
        ld_v8(lp + 8, p + 8);
        float d[8], w[8];
        #pragma unroll
        for (int i = 0; i < 8; i++) {
            d[i] = __fdiv_rn(p[2*i], __fadd_rn(p[2*i+1], EPS));
            w[i] = fminf(fmaxf(p[2*i+1], 0.0f), 1.0f);
        }
        st_v8(out + OFF_LD + 8*j, d[0], d[1], d[2], d[3],
                                  d[4], d[5], d[6], d[7]);
        st_v8(out + OFF_LA + 8*j, w[0], w[1], w[2], w[3],
                                  w[4], w[5], w[6], w[7]);
        // unconditional self-clean (lidar is densely touched, tiny plane)
        st_v8(lp + 0, 0.f, 0.f, 0.f, 0.f, 0.f, 0.f, 0.f, 0.f);
        st_v8(lp + 8, 0.f, 0.f, 0.f, 0.f, 0.f, 0.f, 0.f, 0.f);
    }
}

extern "C" void kernel_launch(void* const* d_in, const int* in_sizes, int n_in,
                              void* d_out, int out_size) {
    const float* means = (const float*)d_in[0];
    const float* sh    = (const float*)d_in[3];
    const float* opa_c = (const float*)d_in[4];
    const float* opa_l = (const float*)d_in[5];
    const float* c2w   = (const float*)d_in[6];
    const float* K     = (const float*)d_in[7];
    const float* l2w   = (const float*)d_in[8];
    float* out = (float*)d_out;

    int n = in_sizes[0] / 3;

    int nt = (n + 3) / 4;
    splat_kernel<<<(nt + 255) / 256, 256>>>(means, sh, opa_c, opa_l,
                                            c2w, K, l2w, n);
    int tot = CAM_T8 + LID_T8;
    finalize_kernel<<<(tot + 255) / 256, 256>>>(out);
}